// round 13
// baseline (speedup 1.0000x reference)
#include <cuda_runtime.h>
#include <math.h>

#define NBATCH 2048

// ---- image layout: plain rows, stride 68 (=17 float4), x stored at idx x+2 ----
// row ry = y+2 (0..66, rows 0,1,66 zero), idx 0,1,66,67 zero pad
// pixel ox: taps = floats 4*ox .. 4*ox+10 = float4 words ox, ox+1, ox+2
#define IMROW 68
#define IMCH  (67 * IMROW)          // 4556 (mult of 4 -> float4-aligned rows)
#define S_W1  13668                 // conv1 weights [c][ky][f][12] = 3960 (float4-aligned)
#define SMEM_FLOATS (S_W1 + 3960)   // 17628 floats = 70512 bytes -> 3 CTAs/SM

// aliases in the image region (dead after conv1):
#define S_C1   0                    // conv1 out [10][15][16] = 2400
#define S_W2P  2400                 // conv2 weights padded [16][10][5][8] = 6400
#define S_P1P  8800                 // pool1 out zero-padded [10][11][12] = 1320
#define S_C2   10120                // conv2 out [16][4][4] = 256
#define S_FL   10376                // flat 64

__device__ __forceinline__ float leaky(float v) { return v > 0.f ? v : 0.01f * v; }

__global__ void __launch_bounds__(256, 3)
cnn_kernel(const float* __restrict__ im,
           const float* __restrict__ w1,
           const float* __restrict__ w2,
           const float* __restrict__ b2,
           const float* __restrict__ lw,
           const float* __restrict__ lb,
           float* __restrict__ out)
{
    extern __shared__ float sm[];
    const int b   = blockIdx.x;
    const int tid = threadIdx.x;

    // ---- zero image + weight regions (halo & pad-lane correctness) ----
    for (int i = tid; i < SMEM_FLOATS; i += 256) sm[i] = 0.f;
    __syncthreads();

    {
        const float2* gim = (const float2*)(im + (size_t)b * 12288);
        for (int i = tid; i < 6144; i += 256) {
            float2 v = gim[i];
            int fi = i << 1;
            int c  = fi >> 12;
            int y  = (fi & 4095) >> 6;
            int x  = fi & 63;
            int base = c * IMCH + (y + 2) * IMROW + x + 2;
            sm[base]     = v.x;
            sm[base + 1] = v.y;
        }
    }
    // conv1 weights: [f][c][ky][kx] -> [c][ky][f][12] (pad lane kx=11 stays 0)
    for (int i = tid; i < 3630; i += 256) {
        int f   = i / 363;
        int rem = i % 363;
        int c   = rem / 121;
        int r2  = rem % 121;
        int ky  = r2 / 11;
        int kx  = r2 % 11;
        sm[S_W1 + ((c * 11 + ky) * 10 + f) * 12 + kx] = w1[i];
    }

    // graph half is analytically constant: softmax == 0.05 (verified exact R1-R12)
    if (tid < 20)
        out[b * 20 + tid] = 0.05f;

    __syncthreads();

    // ---- conv1 (11x11, s4, p2): 15x15 out, 10 filters ----
    // thread = pixel: oy = tid>>4 (0..14), ox = tid&15 (active ox<15) -> 225 of 240
    // inputs: 3 conflict-free LDS.128/row (words ox..ox+2; 8-lane phases hit
    // 8 distinct bank groups); weights: warp-uniform float4 broadcasts.
    const int oy = tid >> 4, ox = tid & 15;
    const bool c1act = (tid < 240) && (ox < 15);
    float acc[10];
    #pragma unroll
    for (int f = 0; f < 10; f++) acc[f] = 0.f;

    if (c1act) {
        #pragma unroll 1
        for (int c = 0; c < 3; c++) {
            const float4* rp = (const float4*)&sm[c * IMCH + (4 * oy) * IMROW] + ox;
            const float4* wp = (const float4*)&sm[S_W1 + (c * 11) * 120];
            #pragma unroll 2
            for (int ky = 0; ky < 11; ky++) {
                const float4* row = rp + ky * 17;
                float4 X0 = row[0];
                float4 X1 = row[1];
                float4 X2 = row[2];
                const float4* wr = wp + ky * 30;
                #pragma unroll
                for (int f = 0; f < 10; f++) {
                    float4 wa = wr[f * 3 + 0];
                    float4 wb = wr[f * 3 + 1];
                    float4 wc = wr[f * 3 + 2];
                    float s = acc[f];
                    s = fmaf(X0.x, wa.x, s); s = fmaf(X0.y, wa.y, s);
                    s = fmaf(X0.z, wa.z, s); s = fmaf(X0.w, wa.w, s);
                    s = fmaf(X1.x, wb.x, s); s = fmaf(X1.y, wb.y, s);
                    s = fmaf(X1.z, wb.z, s); s = fmaf(X1.w, wb.w, s);
                    s = fmaf(X2.x, wc.x, s); s = fmaf(X2.y, wc.y, s);
                    s = fmaf(X2.z, wc.z, s);
                    acc[f] = s;
                }
            }
        }
    }
    __syncthreads();   // image reads done; region reusable

    if (c1act) {
        #pragma unroll
        for (int f = 0; f < 10; f++)
            sm[S_C1 + (f * 15 + oy) * 16 + ox] = leaky(acc[f]);
    }
    // stage conv2 weights padded [f][c][ky][8]
    for (int i = tid; i < 4000; i += 256) {
        int kx = i % 5; int t = i / 5;
        int ky = t % 5; t /= 5;
        int c  = t % 10; int f = t / 10;
        sm[S_W2P + (((f * 10 + c) * 5) + ky) * 8 + kx] = w2[i];
    }
    // zero-fill padded pool1 buffer
    for (int i = tid; i < 1320; i += 256)
        sm[S_P1P + i] = 0.f;
    __syncthreads();

    // ---- maxpool 3x3 s2: 15x15 -> 7x7, write into zero-padded [10][11][12] ----
    for (int i = tid; i < 490; i += 256) {
        int f = i / 49, r = i % 49;
        int py = r / 7, px = r % 7;
        float m = -1e30f;
        #pragma unroll
        for (int dy = 0; dy < 3; dy++)
            #pragma unroll
            for (int dx = 0; dx < 3; dx++)
                m = fmaxf(m, sm[S_C1 + (f * 15 + (2 * py + dy)) * 16 + (2 * px + dx)]);
        sm[S_P1P + (f * 11 + py + 2) * 12 + px + 2] = m;
    }
    __syncthreads();

    // ---- conv2 (5x5, s2, p2): 7x7 -> 4x4, 10 -> 16 ch, guard-free ----
    {
        int f   = tid >> 4;
        int r   = tid & 15;
        int oy2 = r >> 2;
        int ox2 = r & 3;
        float av = b2[f];
        #pragma unroll 1
        for (int c = 0; c < 10; c++) {
            #pragma unroll
            for (int ky = 0; ky < 5; ky++) {
                const float* prow = &sm[S_P1P + (c * 11 + 2 * oy2 + ky) * 12 + 2 * ox2];
                const float4 wv = *(const float4*)&sm[S_W2P + ((f * 10 + c) * 5 + ky) * 8];
                const float  w4 = sm[S_W2P + ((f * 10 + c) * 5 + ky) * 8 + 4];
                av = fmaf(prow[0], wv.x, av);
                av = fmaf(prow[1], wv.y, av);
                av = fmaf(prow[2], wv.z, av);
                av = fmaf(prow[3], wv.w, av);
                av = fmaf(prow[4], w4,  av);
            }
        }
        sm[S_C2 + f * 16 + oy2 * 4 + ox2] = leaky(av);
    }
    __syncthreads();

    // ---- maxpool 2x2 s2: 4x4 -> 2x2, flatten ----
    if (tid < 64) {
        int f = tid >> 2, py = (tid >> 1) & 1, px = tid & 1;
        float m = sm[S_C2 + f * 16 + (2 * py) * 4 + (2 * px)];
        m = fmaxf(m, sm[S_C2 + f * 16 + (2 * py) * 4 + (2 * px + 1)]);
        m = fmaxf(m, sm[S_C2 + f * 16 + (2 * py + 1) * 4 + (2 * px)]);
        m = fmaxf(m, sm[S_C2 + f * 16 + (2 * py + 1) * 4 + (2 * px + 1)]);
        sm[S_FL + tid] = m;   // flat index == tid
    }
    __syncthreads();

    // ---- linear 64 -> 2 + sigmoid ----
    if (tid < 2) {
        float a2 = lb[tid];
        #pragma unroll
        for (int k = 0; k < 64; k++)
            a2 = fmaf(sm[S_FL + k], lw[tid * 64 + k], a2);
        out[NBATCH * 20 + b * 2 + tid] = 1.f / (1.f + __expf(-a2));
    }
}

extern "C" void kernel_launch(void* const* d_in, const int* in_sizes, int n_in,
                              void* d_out, int out_size)
{
    (void)in_sizes; (void)n_in; (void)out_size;
    const float* im = (const float*)d_in[0];
    // d_in[1] = x, d_in[2] = edge_index : dead (graph output is constant 0.05)
    const float* w1 = (const float*)d_in[3];
    const float* w2 = (const float*)d_in[4];
    const float* b2 = (const float*)d_in[5];
    const float* lw = (const float*)d_in[6];
    const float* lb = (const float*)d_in[7];
    float* out = (float*)d_out;

    cudaFuncSetAttribute(cnn_kernel, cudaFuncAttributeMaxDynamicSharedMemorySize,
                         SMEM_FLOATS * sizeof(float));
    cnn_kernel<<<NBATCH, 256, SMEM_FLOATS * sizeof(float)>>>(im, w1, w2, b2, lw, lb, out);
}

// round 14
// speedup vs baseline: 1.2999x; 1.2999x over previous
#include <cuda_runtime.h>
#include <math.h>

#define NBATCH 2048

// ---- image layout: plain rows, stride 68 (=17 float4), x stored at idx x+2 ----
// row ry = y+2 (0..66, rows 0,1,66 zero), idx 0,1,66,67 zero pad
// pixel ox: taps = floats 4*ox .. 4*ox+10
#define IMROW 68
#define IMCH  (67 * IMROW)          // 4556 (mult of 4 -> float4-aligned rows)
#define S_W1  13668                 // conv1 weights [c][ky][f][12] = 3960 (float4-aligned)
#define SMEM_FLOATS (S_W1 + 3960)   // 17628 floats = 70512 bytes -> 3 CTAs/SM

// aliases in the image region (dead after conv1 mainloop):
#define S_TMP  0                    // group-B partials [10][15][16] = 2400
#define S_C1   2400                 // conv1 out [10][15][16] = 2400
#define S_W2P  4800                 // conv2 weights padded [16][10][5][8] = 6400
#define S_P1P  11200                // pool1 out zero-padded [10][11][12] = 1320
#define S_C2   12520                // conv2 out [16][4][4] = 256
#define S_FL   12776                // flat 64 (total 12840 < 13668 ✓)

__device__ __forceinline__ float leaky(float v) { return v > 0.f ? v : 0.01f * v; }

// one (c,ky) reduction row of conv1 for 5 filters x 4 adjacent pixels
__device__ __forceinline__ void c1_row(const float* __restrict__ sm,
                                       int c, int ky, int oy, int pr, int fh,
                                       float acc[5][4])
{
    const float4* row = (const float4*)&sm[c * IMCH + (4 * oy + ky) * IMROW] + 4 * pr;
    float4 X[6];
    #pragma unroll
    for (int j = 0; j < 6; j++) X[j] = row[j];
    const float* xs = (const float*)X;   // pixel d taps = xs[4d+k], k=0..10
    const float* wr = &sm[S_W1 + (c * 11 + ky) * 120 + fh * 60];
    #pragma unroll
    for (int f = 0; f < 5; f++) {
        float4 wa = *(const float4*)(wr + f * 12);
        float4 wb = *(const float4*)(wr + f * 12 + 4);
        float4 wc = *(const float4*)(wr + f * 12 + 8);
        float w[11] = {wa.x, wa.y, wa.z, wa.w,
                       wb.x, wb.y, wb.z, wb.w,
                       wc.x, wc.y, wc.z};
        #pragma unroll
        for (int d = 0; d < 4; d++) {
            float a = acc[f][d];
            #pragma unroll
            for (int k = 0; k < 11; k++)
                a = fmaf(xs[4 * d + k], w[k], a);
            acc[f][d] = a;
        }
    }
}

__global__ void __launch_bounds__(256, 3)
cnn_kernel(const float* __restrict__ im,
           const float* __restrict__ w1,
           const float* __restrict__ w2,
           const float* __restrict__ b2,
           const float* __restrict__ lw,
           const float* __restrict__ lb,
           float* __restrict__ out)
{
    extern __shared__ float sm[];
    const int b   = blockIdx.x;
    const int tid = threadIdx.x;

    // ---- zero image + weight regions (halo & pad-lane correctness) ----
    for (int i = tid; i < SMEM_FLOATS; i += 256) sm[i] = 0.f;
    __syncthreads();

    {
        const float2* gim = (const float2*)(im + (size_t)b * 12288);
        for (int i = tid; i < 6144; i += 256) {
            float2 v = gim[i];
            int fi = i << 1;
            int c  = fi >> 12;
            int y  = (fi & 4095) >> 6;
            int x  = fi & 63;
            int base = c * IMCH + (y + 2) * IMROW + x + 2;
            sm[base]     = v.x;
            sm[base + 1] = v.y;
        }
    }
    // conv1 weights: [f][c][ky][kx] -> [c][ky][f][12] (pad lane kx=11 stays 0)
    for (int i = tid; i < 3630; i += 256) {
        int f   = i / 363;
        int rem = i % 363;
        int c   = rem / 121;
        int r2  = rem % 121;
        int ky  = r2 / 11;
        int kx  = r2 % 11;
        sm[S_W1 + ((c * 11 + ky) * 10 + f) * 12 + kx] = w1[i];
    }

    // graph half is analytically constant: softmax == 0.05 (verified exact R1-R13)
    if (tid < 20)
        out[b * 20 + tid] = 0.05f;

    __syncthreads();

    // ---- conv1 (11x11, s4, p2): 15x15 out, 10 filters, K-split across warp halves ----
    // group A = warps 0-3  (tid 0-119   active): rows c=0 ky0-10, c=1 ky0-4  (16)
    // group B = warps 4-7  (tid 128-247 active): rows c=1 ky5-10, c=2 ky0-10 (17)
    // within group: oy = a>>3 (0..14), pr = (a>>1)&3, fh = a&1
    // pixels ox = 4*pr+d (d=0..3, ox=15 discarded); filters fh*5..fh*5+4
    const bool grpB = (tid >= 128);
    const int  a    = grpB ? (tid - 128) : tid;
    const bool c1act = (a < 120);
    const int  oy = a >> 3, pr = (a >> 1) & 3, fh = a & 1;

    float acc[5][4];
    #pragma unroll
    for (int f = 0; f < 5; f++)
        #pragma unroll
        for (int d = 0; d < 4; d++) acc[f][d] = 0.f;

    if (c1act) {
        if (!grpB) {
            #pragma unroll 1
            for (int ky = 0; ky < 11; ky++) c1_row(sm, 0, ky, oy, pr, fh, acc);
            #pragma unroll 1
            for (int ky = 0; ky < 5;  ky++) c1_row(sm, 1, ky, oy, pr, fh, acc);
        } else {
            #pragma unroll 1
            for (int ky = 5; ky < 11; ky++) c1_row(sm, 1, ky, oy, pr, fh, acc);
            #pragma unroll 1
            for (int ky = 0; ky < 11; ky++) c1_row(sm, 2, ky, oy, pr, fh, acc);
        }
    }
    __syncthreads();   // image reads done; region reusable

    // group B parks raw partials (d contiguous -> float4 at col 4*pr)
    if (grpB && c1act) {
        #pragma unroll
        for (int f = 0; f < 5; f++) {
            const int fg = fh * 5 + f;
            *(float4*)&sm[S_TMP + (fg * 15 + oy) * 16 + 4 * pr] =
                make_float4(acc[f][0], acc[f][1], acc[f][2], acc[f][3]);
        }
    }
    // stage conv2 weights padded [f][c][ky][8]
    for (int i = tid; i < 4000; i += 256) {
        int kx = i % 5; int t = i / 5;
        int ky = t % 5; t /= 5;
        int c  = t % 10; int f = t / 10;
        sm[S_W2P + (((f * 10 + c) * 5) + ky) * 8 + kx] = w2[i];
    }
    // zero-fill padded pool1 buffer
    for (int i = tid; i < 1320; i += 256)
        sm[S_P1P + i] = 0.f;
    __syncthreads();

    // group A combines + leaky -> C1 (col 15 = garbage, never read by pool)
    if (!grpB && c1act) {
        #pragma unroll
        for (int f = 0; f < 5; f++) {
            const int fg = fh * 5 + f;
            float4 p = *(const float4*)&sm[S_TMP + (fg * 15 + oy) * 16 + 4 * pr];
            *(float4*)&sm[S_C1 + (fg * 15 + oy) * 16 + 4 * pr] =
                make_float4(leaky(acc[f][0] + p.x), leaky(acc[f][1] + p.y),
                            leaky(acc[f][2] + p.z), leaky(acc[f][3] + p.w));
        }
    }
    __syncthreads();

    // ---- maxpool 3x3 s2: 15x15 -> 7x7, write into zero-padded [10][11][12] ----
    for (int i = tid; i < 490; i += 256) {
        int f = i / 49, r = i % 49;
        int py = r / 7, px = r % 7;
        float m = -1e30f;
        #pragma unroll
        for (int dy = 0; dy < 3; dy++)
            #pragma unroll
            for (int dx = 0; dx < 3; dx++)
                m = fmaxf(m, sm[S_C1 + (f * 15 + (2 * py + dy)) * 16 + (2 * px + dx)]);
        sm[S_P1P + (f * 11 + py + 2) * 12 + px + 2] = m;
    }
    __syncthreads();

    // ---- conv2 (5x5, s2, p2): 7x7 -> 4x4, 10 -> 16 ch, guard-free ----
    {
        int f   = tid >> 4;
        int r   = tid & 15;
        int oy2 = r >> 2;
        int ox2 = r & 3;
        float av = b2[f];
        #pragma unroll 1
        for (int c = 0; c < 10; c++) {
            #pragma unroll
            for (int ky = 0; ky < 5; ky++) {
                const float* prow = &sm[S_P1P + (c * 11 + 2 * oy2 + ky) * 12 + 2 * ox2];
                const float4 wv = *(const float4*)&sm[S_W2P + ((f * 10 + c) * 5 + ky) * 8];
                const float  w4 = sm[S_W2P + ((f * 10 + c) * 5 + ky) * 8 + 4];
                av = fmaf(prow[0], wv.x, av);
                av = fmaf(prow[1], wv.y, av);
                av = fmaf(prow[2], wv.z, av);
                av = fmaf(prow[3], wv.w, av);
                av = fmaf(prow[4], w4,  av);
            }
        }
        sm[S_C2 + f * 16 + oy2 * 4 + ox2] = leaky(av);
    }
    __syncthreads();

    // ---- maxpool 2x2 s2: 4x4 -> 2x2, flatten ----
    if (tid < 64) {
        int f = tid >> 2, py = (tid >> 1) & 1, px = tid & 1;
        float m = sm[S_C2 + f * 16 + (2 * py) * 4 + (2 * px)];
        m = fmaxf(m, sm[S_C2 + f * 16 + (2 * py) * 4 + (2 * px + 1)]);
        m = fmaxf(m, sm[S_C2 + f * 16 + (2 * py + 1) * 4 + (2 * px)]);
        m = fmaxf(m, sm[S_C2 + f * 16 + (2 * py + 1) * 4 + (2 * px + 1)]);
        sm[S_FL + tid] = m;   // flat index == tid
    }
    __syncthreads();

    // ---- linear 64 -> 2 + sigmoid ----
    if (tid < 2) {
        float a2 = lb[tid];
        #pragma unroll
        for (int k = 0; k < 64; k++)
            a2 = fmaf(sm[S_FL + k], lw[tid * 64 + k], a2);
        out[NBATCH * 20 + b * 2 + tid] = 1.f / (1.f + __expf(-a2));
    }
}

extern "C" void kernel_launch(void* const* d_in, const int* in_sizes, int n_in,
                              void* d_out, int out_size)
{
    (void)in_sizes; (void)n_in; (void)out_size;
    const float* im = (const float*)d_in[0];
    // d_in[1] = x, d_in[2] = edge_index : dead (graph output is constant 0.05)
    const float* w1 = (const float*)d_in[3];
    const float* w2 = (const float*)d_in[4];
    const float* b2 = (const float*)d_in[5];
    const float* lw = (const float*)d_in[6];
    const float* lb = (const float*)d_in[7];
    float* out = (float*)d_out;

    cudaFuncSetAttribute(cnn_kernel, cudaFuncAttributeMaxDynamicSharedMemorySize,
                         SMEM_FLOATS * sizeof(float));
    cnn_kernel<<<NBATCH, 256, SMEM_FLOATS * sizeof(float)>>>(im, w1, w2, b2, lw, lb, out);
}